// round 2
// baseline (speedup 1.0000x reference)
#include <cuda_runtime.h>
#include <cuda_bf16.h>
#include <cstdint>

// ======================= problem constants =======================
#define BN 4096
#define DK 512
#define NTILE 32                 // 4096/128 tiles per dim
#define NTRI  (NTILE * (NTILE + 1) / 2)   // 528 upper-tri tiles

#define MARGINF 0.6f
#define LOF     0.56f            // fp32(0.6 - 0.04)
#define HIF     0.64f            // fp32(0.6 + 0.04)

// ======================= device state ===========================
__device__ __nv_bfloat16 g_xbf[(size_t)BN * DK];     // 4 MB bf16 copy of X
__device__ float         g_norms[BN];                // squared norms (fp32, exact)
__device__ float         g_buf[(size_t)BN * BN];     // compact neg d<HI values
__device__ double        g_pos_loss;
__device__ double        g_negsum;                   // sum(HI - d) over neg d<HI (weighted)
__device__ unsigned int  g_right;
__device__ unsigned int  g_m;                        // count of neg d<HI (weighted; append cursor)
__device__ unsigned int  g_k;                        // num_pairs

// ======================= PTX helpers =============================
__device__ __forceinline__ uint32_t smem_to_u32(const void* p) {
    uint32_t a;
    asm("{ .reg .u64 t; cvta.to.shared.u64 t, %1; cvt.u32.u64 %0, t; }" : "=r"(a) : "l"(p));
    return a;
}
__device__ __forceinline__ void cp16(uint32_t dst, const void* src) {
    asm volatile("cp.async.cg.shared.global [%0], [%1], 16;" :: "r"(dst), "l"(src));
}
#define CP_COMMIT() asm volatile("cp.async.commit_group;" ::: "memory")
#define CP_WAIT(n)  asm volatile("cp.async.wait_group %0;" :: "n"(n) : "memory")

#define LDSM_X4(r, addr) \
    asm volatile("ldmatrix.sync.aligned.m8n8.x4.shared.b16 {%0,%1,%2,%3}, [%4];" \
                 : "=r"((r)[0]), "=r"((r)[1]), "=r"((r)[2]), "=r"((r)[3]) : "r"(addr))

__device__ __forceinline__ void mma16816(float* c, const uint32_t* a, uint32_t b0, uint32_t b1) {
    asm volatile(
        "mma.sync.aligned.m16n8k16.row.col.f32.bf16.bf16.f32 "
        "{%0,%1,%2,%3}, {%4,%5,%6,%7}, {%8,%9}, {%0,%1,%2,%3};"
        : "+f"(c[0]), "+f"(c[1]), "+f"(c[2]), "+f"(c[3])
        : "r"(a[0]), "r"(a[1]), "r"(a[2]), "r"(a[3]), "r"(b0), "r"(b1));
}

#define SWZ(off) ((off) ^ (((off) >> 3) & 0x70))

// ======================= K1: norms + bf16 convert =======================
__global__ void prep_kernel(const float* __restrict__ X) {
    int row  = blockIdx.x * 8 + (threadIdx.x >> 5);
    int lane = threadIdx.x & 31;
    const float* xr = X + (size_t)row * DK;
    float s = 0.0f;
#pragma unroll
    for (int i = 0; i < DK / 32; ++i) {
        float v = xr[lane + i * 32];
        s += v * v;
        g_xbf[(size_t)row * DK + lane + i * 32] = __float2bfloat16(v);
    }
#pragma unroll
    for (int o = 16; o; o >>= 1) s += __shfl_down_sync(0xffffffffu, s, o);
    if (lane == 0) g_norms[row] = s;
}

// ======================= K1b: labels / k / zero state ===================
__global__ void labels_kernel(const int* __restrict__ tgt) {
    __shared__ unsigned cnt[64];
    int tid = threadIdx.x;
    if (tid < 64) cnt[tid] = 0u;
    __syncthreads();
    for (int i = tid; i < BN; i += blockDim.x) atomicAdd(&cnt[tgt[i] & 63], 1u);
    __syncthreads();
    if (tid == 0) {
        unsigned long long np = 0;
        for (int c = 0; c < 64; ++c) np += (unsigned long long)cnt[c] * cnt[c];
        g_k        = (unsigned)((np - (unsigned long long)BN) / 2ull);
        g_pos_loss = 0.0;
        g_negsum   = 0.0;
        g_right    = 0u;
        g_m        = 0u;
    }
}

// ======================= K2: fused GEMM + stats =========================
// One 128x128 output tile per CTA (upper-triangular tiles only; off-diagonal
// tiles carry weight 2). 256 threads = 8 warps in a 4(M) x 2(N) grid; each
// warp computes 32x64 via m16n8k16 bf16 mma.sync. K staged in 8 chunks of 64
// (128-byte SW128-swizzled smem rows), double-buffered cp.async.
//
// smem: [0,512) col norms | [512,1024) col targets | [1024,1088) reduce
//       [2048, 2048+2*32768) A/B tiles (2 stages x (16KB A + 16KB B))
#define SM_SCN  0
#define SM_SCT  512
#define SM_RED  1024
#define SM_TILE 2048
#define SM_TOTAL (SM_TILE + 2 * 32768)

__device__ __forceinline__ void stage_load(uint32_t sbase, int r0, int c0, int kc, int tid) {
    int s = kc & 1;
    uint32_t abase = sbase + SM_TILE + (uint32_t)s * 32768u;
    uint32_t bbase = abase + 16384u;
    int row = tid >> 1, half = tid & 1;
    const char* asrc = (const char*)(g_xbf + (size_t)(r0 + row) * DK + kc * 64 + half * 32);
    const char* bsrc = (const char*)(g_xbf + (size_t)(c0 + row) * DK + kc * 64 + half * 32);
#pragma unroll
    for (int i = 0; i < 4; ++i) {
        uint32_t off = (uint32_t)row * 128u + (uint32_t)half * 64u + (uint32_t)i * 16u;
        uint32_t sw  = SWZ(off);
        cp16(abase + sw, asrc + i * 16);
        cp16(bbase + sw, bsrc + i * 16);
    }
}

__global__ __launch_bounds__(256) void gemm_stats_kernel(const int* __restrict__ tgt) {
    extern __shared__ char smem[];
    const uint32_t sbase = smem_to_u32(smem);
    const int tid  = threadIdx.x;
    const int wid  = tid >> 5;
    const int lane = tid & 31;

    // decode upper-triangular tile index: by >= bx
    int t = blockIdx.x;
    int by = 0;
    while (((by + 1) * (by + 2)) / 2 <= t) ++by;
    int bx = t - (by * (by + 1)) / 2;
    const int r0 = by * 128, c0 = bx * 128;
    const int w2 = (by == bx) ? 1 : 2;

    if (tid < 128) {
        ((float*)(smem + SM_SCN))[tid] = g_norms[c0 + tid];
        ((int*)(smem + SM_SCT))[tid]   = tgt[c0 + tid];
    }

    const int wm = wid & 3;   // 0..3 -> M offset wm*32
    const int wn = wid >> 2;  // 0..1 -> N offset wn*64

    float acc[2][8][4];
#pragma unroll
    for (int mi = 0; mi < 2; ++mi)
#pragma unroll
        for (int ni = 0; ni < 8; ++ni)
#pragma unroll
            for (int r = 0; r < 4; ++r) acc[mi][ni][r] = 0.0f;

    stage_load(sbase, r0, c0, 0, tid);
    CP_COMMIT();

    for (int kc = 0; kc < 8; ++kc) {
        if (kc < 7) { stage_load(sbase, r0, c0, kc + 1, tid); CP_COMMIT(); }
        if (kc < 7) CP_WAIT(1); else CP_WAIT(0);
        __syncthreads();

        uint32_t abase = sbase + SM_TILE + (uint32_t)(kc & 1) * 32768u;
        uint32_t bbase = abase + 16384u;
#pragma unroll
        for (int ks = 0; ks < 4; ++ks) {
            uint32_t a[2][4];
#pragma unroll
            for (int mi = 0; mi < 2; ++mi) {
                uint32_t off = (uint32_t)(wm * 32 + mi * 16 + (lane & 15)) * 128u +
                               (uint32_t)(lane >> 4) * 16u + (uint32_t)ks * 32u;
                LDSM_X4(a[mi], abase + SWZ(off));
            }
            uint32_t b[4][4];
#pragma unroll
            for (int nt = 0; nt < 4; ++nt) {
                uint32_t off = (uint32_t)(wn * 64 + nt * 16 + (lane & 15)) * 128u +
                               (uint32_t)(lane >> 4) * 16u + (uint32_t)ks * 32u;
                LDSM_X4(b[nt], bbase + SWZ(off));
            }
#pragma unroll
            for (int mi = 0; mi < 2; ++mi)
#pragma unroll
                for (int ni = 0; ni < 8; ++ni) {
                    int nt = ni >> 1, hi = ni & 1;
                    mma16816(acc[mi][ni], a[mi], b[nt][hi ? 1 : 0], b[nt][hi ? 3 : 2]);
                }
        }
        __syncthreads();
    }

    // ---------------- epilogue ----------------
    const float* scn = (const float*)(smem + SM_SCN);
    const int*   sct = (const int*)(smem + SM_SCT);

    float pl = 0.0f, ns = 0.0f;
    unsigned right = 0u;

#pragma unroll
    for (int mi = 0; mi < 2; ++mi) {
#pragma unroll
        for (int ni = 0; ni < 8; ++ni) {
#pragma unroll
            for (int r = 0; r < 4; ++r) {
                int il = wm * 32 + mi * 16 + (lane >> 2) + ((r >> 1) << 3);
                int jl = wn * 64 + ni * 8 + ((lane & 3) << 1) + (r & 1);
                int i_g = r0 + il;
                int j_g = c0 + jl;
                float g  = acc[mi][ni][r];
                float n_i = g_norms[i_g];               // L1-resident after first touch
                float sq  = n_i + scn[jl] - 2.0f * g;
                float d   = (i_g != j_g && sq > 0.0f) ? sqrtf(sq) : 0.0f;
                bool  pos = (tgt[i_g] == sct[jl]);
                bool  hit = (!pos) && (d < HIF);
                if (pos) {
                    right += (d < MARGINF) ? (unsigned)w2 : 0u;
                    if (d > LOF) pl += (float)w2 * (d - LOF);
                } else {
                    right += (d >= MARGINF) ? (unsigned)w2 : 0u;
                }
                unsigned mask = __ballot_sync(0xffffffffu, hit);
                if (mask) {
                    int leader = __ffs(mask) - 1;
                    unsigned base = 0u;
                    if (lane == leader)
                        base = atomicAdd(&g_m, (unsigned)__popc(mask) * (unsigned)w2);
                    base = __shfl_sync(0xffffffffu, base, leader);
                    if (hit) {
                        unsigned off = (unsigned)__popc(mask & ((1u << lane) - 1u)) * (unsigned)w2;
                        g_buf[base + off] = d;
                        if (w2 == 2) g_buf[base + off + 1] = d;
                        ns += (float)w2 * (HIF - d);
                    }
                }
            }
        }
    }

    // block reduce -> global atomics
#pragma unroll
    for (int o = 16; o; o >>= 1) {
        pl    += __shfl_down_sync(0xffffffffu, pl, o);
        ns    += __shfl_down_sync(0xffffffffu, ns, o);
        right += __shfl_down_sync(0xffffffffu, right, o);
    }
    float*    rpl = (float*)(smem + SM_RED);
    float*    rns = (float*)(smem + SM_RED + 32);
    unsigned* rrt = (unsigned*)(smem + SM_RED + 64);
    if (lane == 0) { rpl[wid] = pl; rns[wid] = ns; rrt[wid] = right; }
    __syncthreads();
    if (tid == 0) {
        float plb = 0.0f, nsb = 0.0f; unsigned rb = 0u;
#pragma unroll
        for (int w = 0; w < 8; ++w) { plb += rpl[w]; nsb += rns[w]; rb += rrt[w]; }
        atomicAdd(&g_pos_loss, (double)plb);
        atomicAdd(&g_negsum, (double)nsb);
        atomicAdd(&g_right, rb);
    }
}

// ======================= K3: exact select + finalize ====================
__global__ void select_finalize_kernel(float* __restrict__ out, int out_size) {
    __shared__ unsigned hist[2048];
    __shared__ unsigned sh_b0, sh_b1, sh_b2, sh_r;
    __shared__ double   rsm[32];

    const unsigned k = g_k;
    const unsigned m = g_m;
    const int tid = threadIdx.x;
    const int nt  = blockDim.x;
    __shared__ double sh_negloss;
    double negloss = 0.0;

    if (m > k) {
        // exact radix select for the k-th smallest (0-indexed) over g_buf[0..m)
        for (int b = tid; b < 2048; b += nt) hist[b] = 0u;
        __syncthreads();
        for (unsigned idx = tid; idx < m; idx += nt)
            atomicAdd(&hist[__float_as_uint(g_buf[idx]) >> 21], 1u);
        __syncthreads();
        if (tid == 0) {
            unsigned r = k; int b = 0;
            for (; b < 2048; ++b) { if (r < hist[b]) break; r -= hist[b]; }
            sh_b0 = (unsigned)b; sh_r = r;
        }
        __syncthreads();
        unsigned b0 = sh_b0;
        for (int b = tid; b < 2048; b += nt) hist[b] = 0u;
        __syncthreads();
        for (unsigned idx = tid; idx < m; idx += nt) {
            unsigned key = __float_as_uint(g_buf[idx]);
            if ((key >> 21) == b0) atomicAdd(&hist[(key >> 10) & 2047u], 1u);
        }
        __syncthreads();
        if (tid == 0) {
            unsigned r = sh_r; int b = 0;
            for (; b < 2048; ++b) { if (r < hist[b]) break; r -= hist[b]; }
            sh_b1 = (unsigned)b; sh_r = r;
        }
        __syncthreads();
        unsigned pref = (b0 << 11) | sh_b1;
        for (int b = tid; b < 1024; b += nt) hist[b] = 0u;
        __syncthreads();
        for (unsigned idx = tid; idx < m; idx += nt) {
            unsigned key = __float_as_uint(g_buf[idx]);
            if ((key >> 10) == pref) atomicAdd(&hist[key & 1023u], 1u);
        }
        __syncthreads();
        if (tid == 0) {
            unsigned r = sh_r; int b = 0;
            for (; b < 1024; ++b) { if (r < hist[b]) break; r -= hist[b]; }
            sh_b2 = (unsigned)b;
        }
        __syncthreads();
        unsigned thr_key = (sh_b0 << 21) | (sh_b1 << 10) | sh_b2;
        double acc = 0.0;
        for (unsigned idx = tid; idx < m; idx += nt) {
            float v = g_buf[idx];
            if (__float_as_uint(v) < thr_key) acc += (double)(HIF - v);
        }
#pragma unroll
        for (int o = 16; o; o >>= 1) acc += __shfl_down_sync(0xffffffffu, acc, o);
        if ((tid & 31) == 0) rsm[tid >> 5] = acc;
        __syncthreads();
        if (tid == 0) {
            double s = 0.0;
            for (int w = 0; w < (nt >> 5); ++w) s += rsm[w];
            sh_negloss = s;
        }
        __syncthreads();
        negloss = sh_negloss;
    } else {
        negloss = g_negsum;  // threshold >= HI: condition reduces to d < HI
    }

    if (tid == 0) {
        double loss = (g_pos_loss + negloss) / (2.0 * (double)k);
        double accy = (double)g_right / ((double)BN * (double)BN);
        out[0] = (float)loss;
        if (out_size > 1) out[1] = (float)accy;
    }
}

// ======================= launch ========================================
extern "C" void kernel_launch(void* const* d_in, const int* in_sizes, int n_in,
                              void* d_out, int out_size) {
    (void)in_sizes; (void)n_in;
    const float* X   = (const float*)d_in[0];
    const int*   tgt = (const int*)d_in[1];
    float*       out = (float*)d_out;

    cudaFuncSetAttribute(gemm_stats_kernel,
                         cudaFuncAttributeMaxDynamicSharedMemorySize, SM_TOTAL);

    prep_kernel<<<BN / 8, 256>>>(X);
    labels_kernel<<<1, 256>>>(tgt);
    gemm_stats_kernel<<<NTRI, 256, SM_TOTAL>>>(tgt);
    select_finalize_kernel<<<1, 1024>>>(out, out_size);
}